// round 10
// baseline (speedup 1.0000x reference)
#include <cuda_runtime.h>

// FINAL (confirmed over 5 runs): masked per-joint MSE loss, HBM-bound
// streaming reduction at the achieved-HBM ceiling.
// Loss per joint (3 floats): d = p - l; s2 = d2^2;
// term = (p2 > 0.5) ? (d0^2+d1^2+d2^2)/3 : s2 ; answer = sum(term)/B.
// Layout: [B, 54] fp32 -> B*18 joints; 4 joints = 3 float4 per iteration.
// Config: grid-stride loop (dense sweep window = DRAM page locality),
// compiler-chosen unrolling (forcing unroll-1 cost 3us), 6x LDG.128/body,
// grid 148*16 x 256, warp+smem reduce, one atomicAdd/block, init kernel.
// Measured 68.8-70.4us kernel @ 6.5-6.65 TB/s (81-84% of HBM3e spec).
// Rejected by measurement: __ldcs+unroll2, fused completion counter,
// per-warp contiguous blocking (-7us locality), single-wave+memset (tie).

__device__ __forceinline__ float joint_term(float p0, float p1, float p2,
                                            float l0, float l1, float l2) {
    float d0 = p0 - l0, d1 = p1 - l1, d2 = p2 - l2;
    float s2 = d2 * d2;
    float full = (d0 * d0 + d1 * d1 + s2) * (1.0f / 3.0f);
    return (p2 > 0.5f) ? full : s2;
}

__global__ void init_out_kernel(float* out) {
    if (threadIdx.x == 0) out[0] = 0.0f;
}

__global__ void __launch_bounds__(256)
loss_kernel(const float4* __restrict__ P, const float4* __restrict__ L,
            float* __restrict__ out, int ngroups, float inv_b) {
    float acc = 0.0f;
    int stride = gridDim.x * blockDim.x;
    for (int g = blockIdx.x * blockDim.x + threadIdx.x; g < ngroups; g += stride) {
        int base = 3 * g;
        float4 pa = P[base + 0];
        float4 pb = P[base + 1];
        float4 pc = P[base + 2];
        float4 la = L[base + 0];
        float4 lb = L[base + 1];
        float4 lc = L[base + 2];
        // 4 joints packed across the 3 float4s
        acc += joint_term(pa.x, pa.y, pa.z, la.x, la.y, la.z);
        acc += joint_term(pa.w, pb.x, pb.y, la.w, lb.x, lb.y);
        acc += joint_term(pb.z, pb.w, pc.x, lb.z, lb.w, lc.x);
        acc += joint_term(pc.y, pc.z, pc.w, lc.y, lc.z, lc.w);
    }

    // warp reduce
    #pragma unroll
    for (int off = 16; off; off >>= 1)
        acc += __shfl_down_sync(0xFFFFFFFFu, acc, off);

    __shared__ float ws[8];
    int lane = threadIdx.x & 31;
    int wid  = threadIdx.x >> 5;
    if (lane == 0) ws[wid] = acc;
    __syncthreads();
    if (wid == 0) {
        acc = (lane < 8) ? ws[lane] : 0.0f;
        #pragma unroll
        for (int off = 4; off; off >>= 1)
            acc += __shfl_down_sync(0xFFFFFFFFu, acc, off);
        if (lane == 0) atomicAdd(out, acc * inv_b);
    }
}

extern "C" void kernel_launch(void* const* d_in, const int* in_sizes, int n_in,
                              void* d_out, int out_size) {
    const float4* P = (const float4*)d_in[0];
    const float4* L = (const float4*)d_in[1];
    float* out = (float*)d_out;

    long long total_floats = (long long)in_sizes[0];     // B * 54
    long long B = total_floats / 54;
    int ngroups = (int)(total_floats / 12);              // 4-joint groups

    init_out_kernel<<<1, 32>>>(out);

    const int threads = 256;
    const int blocks = 148 * 16;                         // champion grid
    loss_kernel<<<blocks, threads>>>(P, L, out, ngroups, 1.0f / (float)B);
}

// round 11
// speedup vs baseline: 1.0224x; 1.0224x over previous
#include <cuda_runtime.h>

// FINAL (champion, 6 confirmation runs): masked per-joint MSE loss,
// HBM-bound streaming reduction at the achieved-HBM ceiling.
// Loss per joint (3 floats): d = p - l; s2 = d2^2;
// term = (p2 > 0.5) ? (d0^2+d1^2+d2^2)/3 : s2 ; answer = sum(term)/B.
// Layout: [B, 54] fp32 -> B*18 joints; 4 joints = 3 float4 per iteration.
// Config: grid-stride loop (dense sweep window = DRAM page locality),
// compiler-chosen unrolling, 6x LDG.128/body, grid 148*16 x 256 threads,
// warp+smem reduce, one atomicAdd/block, init kernel zeroes poisoned d_out.
// Measured 68.8-70.4us kernel @ 6.5-6.65 TB/s (81-84% of HBM3e spec);
// dur 70.2-71.7us (fixed ~1.5us harness/graph gap).
// Rejected by measurement: __ldcs+unroll2 (occ loss), fused completion
// counter (-1us), per-warp contiguous blocking (-7us locality), forced
// unroll-1 (-3us MLP), single-wave grid + memset (tie).

__device__ __forceinline__ float joint_term(float p0, float p1, float p2,
                                            float l0, float l1, float l2) {
    float d0 = p0 - l0, d1 = p1 - l1, d2 = p2 - l2;
    float s2 = d2 * d2;
    float full = (d0 * d0 + d1 * d1 + s2) * (1.0f / 3.0f);
    return (p2 > 0.5f) ? full : s2;
}

__global__ void init_out_kernel(float* out) {
    if (threadIdx.x == 0) out[0] = 0.0f;
}

__global__ void __launch_bounds__(256)
loss_kernel(const float4* __restrict__ P, const float4* __restrict__ L,
            float* __restrict__ out, int ngroups, float inv_b) {
    float acc = 0.0f;
    int stride = gridDim.x * blockDim.x;
    for (int g = blockIdx.x * blockDim.x + threadIdx.x; g < ngroups; g += stride) {
        int base = 3 * g;
        float4 pa = P[base + 0];
        float4 pb = P[base + 1];
        float4 pc = P[base + 2];
        float4 la = L[base + 0];
        float4 lb = L[base + 1];
        float4 lc = L[base + 2];
        // 4 joints packed across the 3 float4s
        acc += joint_term(pa.x, pa.y, pa.z, la.x, la.y, la.z);
        acc += joint_term(pa.w, pb.x, pb.y, la.w, lb.x, lb.y);
        acc += joint_term(pb.z, pb.w, pc.x, lb.z, lb.w, lc.x);
        acc += joint_term(pc.y, pc.z, pc.w, lc.y, lc.z, lc.w);
    }

    // warp reduce
    #pragma unroll
    for (int off = 16; off; off >>= 1)
        acc += __shfl_down_sync(0xFFFFFFFFu, acc, off);

    __shared__ float ws[8];
    int lane = threadIdx.x & 31;
    int wid  = threadIdx.x >> 5;
    if (lane == 0) ws[wid] = acc;
    __syncthreads();
    if (wid == 0) {
        acc = (lane < 8) ? ws[lane] : 0.0f;
        #pragma unroll
        for (int off = 4; off; off >>= 1)
            acc += __shfl_down_sync(0xFFFFFFFFu, acc, off);
        if (lane == 0) atomicAdd(out, acc * inv_b);
    }
}

extern "C" void kernel_launch(void* const* d_in, const int* in_sizes, int n_in,
                              void* d_out, int out_size) {
    const float4* P = (const float4*)d_in[0];
    const float4* L = (const float4*)d_in[1];
    float* out = (float*)d_out;

    long long total_floats = (long long)in_sizes[0];     // B * 54
    long long B = total_floats / 54;
    int ngroups = (int)(total_floats / 12);              // 4-joint groups

    init_out_kernel<<<1, 32>>>(out);

    const int threads = 256;
    const int blocks = 148 * 16;                         // champion grid
    loss_kernel<<<blocks, threads>>>(P, L, out, ngroups, 1.0f / (float)B);
}

// round 12
// speedup vs baseline: 1.0228x; 1.0005x over previous
#include <cuda_runtime.h>

// FINAL (champion, 7 confirmation runs; best: 70.14us dur / 68.35us kernel
// @ 6.69 TB/s = 83.6% of HBM3e spec): masked per-joint MSE loss, HBM-bound
// streaming reduction at the achieved-HBM ceiling.
// Loss per joint (3 floats): d = p - l; s2 = d2^2;
// term = (p2 > 0.5) ? (d0^2+d1^2+d2^2)/3 : s2 ; answer = sum(term)/B.
// Layout: [B, 54] fp32 -> B*18 joints; 4 joints = 3 float4 per iteration.
// Config: grid-stride loop (dense sweep window = DRAM page locality),
// compiler-chosen unrolling, 6x LDG.128/body, grid 148*16 x 256 threads,
// warp+smem reduce, one atomicAdd/block, init kernel zeroes poisoned d_out.
// Rejected by measurement (R2-R7): __ldcs+unroll2 (occ loss), fused
// completion counter (-1us), per-warp contiguous blocking (-7us locality),
// forced unroll-1 (-3us MLP), single-wave grid + memset (tie).

__device__ __forceinline__ float joint_term(float p0, float p1, float p2,
                                            float l0, float l1, float l2) {
    float d0 = p0 - l0, d1 = p1 - l1, d2 = p2 - l2;
    float s2 = d2 * d2;
    float full = (d0 * d0 + d1 * d1 + s2) * (1.0f / 3.0f);
    return (p2 > 0.5f) ? full : s2;
}

__global__ void init_out_kernel(float* out) {
    if (threadIdx.x == 0) out[0] = 0.0f;
}

__global__ void __launch_bounds__(256)
loss_kernel(const float4* __restrict__ P, const float4* __restrict__ L,
            float* __restrict__ out, int ngroups, float inv_b) {
    float acc = 0.0f;
    int stride = gridDim.x * blockDim.x;
    for (int g = blockIdx.x * blockDim.x + threadIdx.x; g < ngroups; g += stride) {
        int base = 3 * g;
        float4 pa = P[base + 0];
        float4 pb = P[base + 1];
        float4 pc = P[base + 2];
        float4 la = L[base + 0];
        float4 lb = L[base + 1];
        float4 lc = L[base + 2];
        // 4 joints packed across the 3 float4s
        acc += joint_term(pa.x, pa.y, pa.z, la.x, la.y, la.z);
        acc += joint_term(pa.w, pb.x, pb.y, la.w, lb.x, lb.y);
        acc += joint_term(pb.z, pb.w, pc.x, lb.z, lb.w, lc.x);
        acc += joint_term(pc.y, pc.z, pc.w, lc.y, lc.z, lc.w);
    }

    // warp reduce
    #pragma unroll
    for (int off = 16; off; off >>= 1)
        acc += __shfl_down_sync(0xFFFFFFFFu, acc, off);

    __shared__ float ws[8];
    int lane = threadIdx.x & 31;
    int wid  = threadIdx.x >> 5;
    if (lane == 0) ws[wid] = acc;
    __syncthreads();
    if (wid == 0) {
        acc = (lane < 8) ? ws[lane] : 0.0f;
        #pragma unroll
        for (int off = 4; off; off >>= 1)
            acc += __shfl_down_sync(0xFFFFFFFFu, acc, off);
        if (lane == 0) atomicAdd(out, acc * inv_b);
    }
}

extern "C" void kernel_launch(void* const* d_in, const int* in_sizes, int n_in,
                              void* d_out, int out_size) {
    const float4* P = (const float4*)d_in[0];
    const float4* L = (const float4*)d_in[1];
    float* out = (float*)d_out;

    long long total_floats = (long long)in_sizes[0];     // B * 54
    long long B = total_floats / 54;
    int ngroups = (int)(total_floats / 12);              // 4-joint groups

    init_out_kernel<<<1, 32>>>(out);

    const int threads = 256;
    const int blocks = 148 * 16;                         // champion grid
    loss_kernel<<<blocks, threads>>>(P, L, out, ngroups, 1.0f / (float)B);
}